// round 14
// baseline (speedup 1.0000x reference)
#include <cuda_runtime.h>
#include <cstdint>

// TinyRNN: B=4096, T=2048, I=1, H=12, O=2
// 4 lanes/batch; lane k owns rows {3k..3k+2}; 8 batches/warp;
// 128-thread CTAs (32 batches), grid=128 -> 512 warps (1/SMSP on 128 SMs).
// Exchange via same-warp shared memory, NO syncwarp inside step (validated),
// LANE-MAJOR layout: slot float m' = 4*i + k; six ld.shared.b64 give f32x2
// operands directly; arrival-ordered fma2 tree; tanh via MUFU.TANH.
// R14: warp-local x prefetch (no __syncthreads; warps fully decoupled) and
// x-load/U-FFMAs placed in the LDS shadow (after the train).

#define T_TOTAL 2048
#define NCHUNK  32
#define CH      64
#define XSTRIDE 68   // 64 + 4 pad
#define EXSTRIDE 20  // floats per group slot (80B: 16B-aligned, conflict-free)

__device__ __forceinline__ uint64_t pack2(float lo, float hi) {
    uint64_t r; asm("mov.b64 %0, {%1, %2};" : "=l"(r) : "f"(lo), "f"(hi)); return r;
}
__device__ __forceinline__ void unpack2(uint64_t v, float &lo, float &hi) {
    asm("mov.b64 {%0, %1}, %2;" : "=f"(lo), "=f"(hi) : "l"(v));
}
__device__ __forceinline__ uint64_t mul2(uint64_t a, uint64_t b) {
    uint64_t r; asm("mul.rn.f32x2 %0, %1, %2;" : "=l"(r) : "l"(a), "l"(b)); return r;
}
__device__ __forceinline__ uint64_t fma2(uint64_t a, uint64_t b, uint64_t c) {
    uint64_t r; asm("fma.rn.f32x2 %0, %1, %2, %3;" : "=l"(r) : "l"(a), "l"(b), "l"(c)); return r;
}
__device__ __forceinline__ uint64_t add2(uint64_t a, uint64_t b) {
    uint64_t r; asm("add.rn.f32x2 %0, %1, %2;" : "=l"(r) : "l"(a), "l"(b)); return r;
}
__device__ __forceinline__ float tanhf_hw(float x) {
    float r; asm("tanh.approx.f32 %0, %1;" : "=f"(r) : "f"(x)); return r;
}

__global__ void __launch_bounds__(128, 1) tinyrnn_kernel(
    const float* __restrict__ x,       // [4096, 2048, 1]
    const float* __restrict__ W_ih,    // [12, 1]
    const float* __restrict__ W_hh,    // [12, 12]
    const float* __restrict__ b_ih,    // [12]
    const float* __restrict__ b_hh,    // [12]
    const float* __restrict__ W_head,  // [2, 12]
    const float* __restrict__ b_head,  // [2]
    float* __restrict__ out)           // [4096, 2]
{
    __shared__ float sx[2][32 * XSTRIDE];
    __shared__ __align__(16) float sex[32 * EXSTRIDE];

    const int tid  = threadIdx.x;
    const int lane = tid & 31;
    const int warp = tid >> 5;
    const int k    = lane & 3;              // lane within 4-lane group
    const int wb   = lane >> 2;             // group within warp (0..7)
    const int bic  = warp * 8 + wb;         // batch in CTA (0..31)
    const int batch = blockIdx.x * 32 + bic;

    // weights per owned row r=3k+i, for lane-major pairs:
    // quad q pair a = cols (q, 3+q) [lanes 0,1]; pair b = cols (6+q, 9+q)
    uint64_t WA[3][3], WB[3][3];
    float A[3], Bx[3];
#pragma unroll
    for (int i = 0; i < 3; i++) {
        const int r = 3 * k + i;
#pragma unroll
        for (int q = 0; q < 3; q++) {
            WA[i][q] = pack2(W_hh[r * 12 + q],     W_hh[r * 12 + 3 + q]);
            WB[i][q] = pack2(W_hh[r * 12 + 6 + q], W_hh[r * 12 + 9 + q]);
        }
        A[i]  = b_ih[r] + b_hh[r];
        Bx[i] = W_ih[r];
    }

    // exchange slot addresses: float m' = 4*i + k  (lane-major)
    const unsigned exb = (unsigned)__cvta_generic_to_shared(&sex[bic * EXSTRIDE]);
    const unsigned st0 = exb + 4u * (unsigned)k;        // h0 -> quad 0
    const unsigned st1 = st0 + 16u;                     // h1 -> quad 1
    const unsigned st2 = st0 + 32u;                     // h2 -> quad 2

    // warp-local x prefetch: this warp's 8 batches, 64 steps = 128 float4;
    // 4 float4 per lane per chunk.
    const float* xwarp = x + ((size_t)blockIdx.x * 32 + warp * 8) * T_TOTAL;
    auto prefetch = [&](int c, int buf) {
#pragma unroll
        for (int rr = 0; rr < 4; rr++) {
            int flat = rr * 32 + lane;      // 0..127
            int b    = flat >> 4;           // 0..7 (batch within warp)
            int q    = flat & 15;           // float4 within chunk
            const float* src = xwarp + (size_t)b * T_TOTAL + c * CH + q * 4;
            unsigned dst = (unsigned)__cvta_generic_to_shared(
                &sx[buf][(warp * 8 + b) * XSTRIDE + q * 4]);
            asm volatile("cp.async.ca.shared.global [%0], [%1], 16;\n"
                         :: "r"(dst), "l"(src));
        }
        asm volatile("cp.async.commit_group;\n");
    };

    prefetch(0, 0);

    float h0 = 0.0f, h1 = 0.0f, h2 = 0.0f;  // own rows 3k..3k+2

    for (int c = 0; c < NCHUNK; c++) {
        const int cur = c & 1;
        if (c + 1 < NCHUNK) {
            prefetch(c + 1, cur ^ 1);
            asm volatile("cp.async.wait_group 1;\n");
        } else {
            asm volatile("cp.async.wait_group 0;\n");
        }
        __syncwarp();   // publish cp.async results across the warp's lanes

        const float* xs = &sx[cur][bic * XSTRIDE];

#pragma unroll 4
        for (int tt = 0; tt < CH; tt++) {
            // STS h_i immediately followed by quad-i's two b64 loads
            // (same-warp MIO program order; each b64 IS one f32x2 operand).
            uint64_t P0a, P0b, P1a, P1b, P2a, P2b;
            asm volatile("st.shared.f32 [%0], %1;" :: "r"(st0), "f"(h0));
            asm volatile("ld.shared.b64 %0, [%1];" : "=l"(P0a) : "r"(exb));
            asm volatile("ld.shared.b64 %0, [%1];" : "=l"(P0b) : "r"(exb + 8u));
            asm volatile("st.shared.f32 [%0], %1;" :: "r"(st1), "f"(h1));
            asm volatile("ld.shared.b64 %0, [%1];" : "=l"(P1a) : "r"(exb + 16u));
            asm volatile("ld.shared.b64 %0, [%1];" : "=l"(P1b) : "r"(exb + 24u));
            asm volatile("st.shared.f32 [%0], %1;" :: "r"(st2), "f"(h2));
            asm volatile("ld.shared.b64 %0, [%1];" : "=l"(P2a) : "r"(exb + 32u));
            asm volatile("ld.shared.b64 %0, [%1];" : "=l"(P2b) : "r"(exb + 40u));

            // x load + bias terms in the LDS shadow (independent of h)
            const float xt = xs[tt];
            const uint64_t U0 = pack2(fmaf(xt, Bx[0], A[0]), 0.0f);
            const uint64_t U1 = pack2(fmaf(xt, Bx[1], A[1]), 0.0f);
            const uint64_t U2 = pack2(fmaf(xt, Bx[2], A[2]), 0.0f);

            float hn[3];
            const uint64_t UU[3] = {U0, U1, U2};
#pragma unroll
            for (int i = 0; i < 3; i++) {
                // arrival-ordered: 0a,0b,1a,1b,2a,2b; two parallel chains
                uint64_t aA = fma2(WA[i][0], P0a, UU[i]);
                uint64_t aB = mul2(WB[i][0], P0b);
                aA = fma2(WA[i][1], P1a, aA);
                aB = fma2(WB[i][1], P1b, aB);
                aA = fma2(WA[i][2], P2a, aA);
                aB = fma2(WB[i][2], P2b, aB);
                float lo, hi;
                unpack2(add2(aA, aB), lo, hi);
                hn[i] = tanhf_hw(lo + hi);
            }
            h0 = hn[0]; h1 = hn[1]; h2 = hn[2];
        }
    }

    // --- head: rebuild full h via shfl (one-time; negligible) ---
    float g[12];
    g[3 * k + 0] = h0; g[3 * k + 1] = h1; g[3 * k + 2] = h2;
#pragma unroll
    for (int d = 1; d < 4; d++) {
        const int p = k ^ d;
        g[3 * p + 0] = __shfl_xor_sync(0xffffffffu, h0, d, 4);
        g[3 * p + 1] = __shfl_xor_sync(0xffffffffu, h1, d, 4);
        g[3 * p + 2] = __shfl_xor_sync(0xffffffffu, h2, d, 4);
    }

    if (k == 0) {
        float o0 = b_head[0];
        float o1 = b_head[1];
#pragma unroll
        for (int m = 0; m < 12; m++) {
            o0 = fmaf(W_head[m],      g[m], o0);
            o1 = fmaf(W_head[12 + m], g[m], o1);
        }
        out[batch * 2 + 0] = o0;
        out[batch * 2 + 1] = o1;
    }
}

extern "C" void kernel_launch(void* const* d_in, const int* in_sizes, int n_in,
                              void* d_out, int out_size)
{
    const float* x      = (const float*)d_in[0];
    const float* W_ih   = (const float*)d_in[1];
    const float* W_hh   = (const float*)d_in[2];
    const float* b_ih   = (const float*)d_in[3];
    const float* b_hh   = (const float*)d_in[4];
    const float* W_head = (const float*)d_in[5];
    const float* b_head = (const float*)d_in[6];
    float* out = (float*)d_out;

    tinyrnn_kernel<<<128, 128>>>(x, W_ih, W_hh, b_ih, b_hh, W_head, b_head, out);
}